// round 5
// baseline (speedup 1.0000x reference)
#include <cuda_runtime.h>
#include <cuda_bf16.h>
#include <math.h>

#define BS   16
#define M    256
#define NC   80
#define NA   3
#define S0   160
#define S1   80
#define S2   40
#define NG0  (S0*S0)   // 25600
#define NG1  (S1*S1)   // 6400
#define NG2  (S2*S2)   // 1600
#define NG   (NG0+NG1+NG2)  // 33600
#define LOFF1 NG0
#define LOFF2 (NG0+NG1)

// Flat float32 output layout: [txys | whs | scores | anchs | masks]
#define OFF_TXY  0LL
#define OFF_WH   (3225600LL)
#define OFF_SC   (6451200LL)
#define OFF_ANCH (135475200LL)
#define OFF_MASK (138700800LL)

// ---------------- scratch (device globals; no allocation) ----------------
static __device__ int   g_cnt[BS*NG];
static __device__ int   g_minm[BS*NG];
static __device__ int   g_claims[BS*3*M*3];
static __device__ float g_tx[BS*NG];
static __device__ float g_ty[BS*NG];
static __device__ float g_tw[BS*NG];
static __device__ float g_th[BS*NG];
static __device__ int   g_lab[BS*NG];
static __device__ int   g_fg[BS*NG];
static __device__ int   g_lab64;   // 1 if gt_labels buffer is int64, 0 if int32

// streaming stores (write-once data; keep L2 for scratch)
__device__ __forceinline__ void stcs_f (float* p, float v)  { __stcs(p, v); }
__device__ __forceinline__ void stcs_f2(float* p, float2 v) { __stcs((float2*)p, v); }
__device__ __forceinline__ void stcs_f4(float4* p, float4 v){ __stcs(p, v); }

// ---------------- K_detect: label dtype sniff (int64 vs int32), parallel ---
// int64 LE with values < NC: every odd 32-bit word is 0. For int32 random
// labels in [0,80), P(128 odd words all zero) = (1/80)^128 ~ 0.
__global__ void k_detect(const int* __restrict__ labels_raw) {
    int i = threadIdx.x;             // 0..127
    int ok = (labels_raw[2*i + 1] == 0) &&
             ((unsigned)labels_raw[2*i] < (unsigned)NC);
    int all = __syncthreads_and(ok);
    if (i == 0) g_lab64 = all;
}

// ---------------- K0: init (must run every replay; graph is replayed) ------
__global__ void k_init() {
    int i = blockIdx.x * blockDim.x + threadIdx.x;
    if (i < BS*NG) { g_cnt[i] = 0; g_minm[i] = 0x7fffffff; }
}

// ---------------- K1: each (b, level, m) claims its 3 nearest cells --------
__global__ void k_claim(const float* __restrict__ gt_cxy,
                        const float* __restrict__ mask_gt,
                        const float* __restrict__ strides) {
    int t = blockIdx.x * blockDim.x + threadIdx.x;
    if (t >= BS*3*M) return;
    int m = t % M;
    int l = (t / M) % 3;
    int b = t / (M*3);

    int cbase = ((b*3 + l)*M + m)*3;
    g_claims[cbase+0] = -1; g_claims[cbase+1] = -1; g_claims[cbase+2] = -1;
    if (!(mask_gt[b*M + m] > 0.0f)) return;

    float stride = strides[l];
    int s    = (l==0) ? S0 : (l==1) ? S1 : S2;
    int loff = (l==0) ? 0  : (l==1) ? LOFF1 : LOFF2;

    float cx = __fdiv_rn(gt_cxy[(b*M + m)*2 + 0], stride);
    float cy = __fdiv_rn(gt_cxy[(b*M + m)*2 + 1], stride);

    int ix0 = (int)floorf(cx); ix0 = min(max(ix0, 0), s-1);
    int iy0 = (int)floorf(cy); iy0 = min(max(iy0, 0), s-1);
    int x0 = max(ix0-2, 0), x1 = min(ix0+2, s-1);
    int y0 = max(iy0-2, 0), y1 = min(iy0+2, s-1);

    // top-3 smallest metric over the 5x5 clamped window.
    // In-window 3rd-best <= 2.0 + eps; any out-of-window metric >= 2.5 - eps,
    // so set equality with full-grid lax.top_k holds. Strict-< insertion with
    // ascending flat-idx scan reproduces top_k's smaller-index tie-break.
    float v0 = 1e30f, v1 = 1e30f, v2 = 1e30f;
    int   i0 = 0,     i1 = 0,     i2 = 0;
    for (int iy = y0; iy <= y1; iy++) {
        float dy = fabsf((float)iy + 0.5f - cy);
        for (int ix = x0; ix <= x1; ix++) {
            // identical fp expression & add order as reference: |dx| + |dy|
            float v = fabsf((float)ix + 0.5f - cx) + dy;
            int idx = iy*s + ix;
            if (v < v0)      { v2=v1; i2=i1; v1=v0; i1=i0; v0=v; i0=idx; }
            else if (v < v1) { v2=v1; i2=i1; v1=v; i1=idx; }
            else if (v < v2) { v2=v; i2=idx; }
        }
    }
    int cells[3] = {i0, i1, i2};
    #pragma unroll
    for (int k = 0; k < 3; k++) {
        int c = cells[k];
        g_claims[cbase + k] = c;
        atomicAdd(&g_cnt [b*NG + loff + c], 1);
        atomicMin(&g_minm[b*NG + loff + c], m);
    }
}

// ---------------- K2: per-cell resolve + gather targets --------------------
__global__ void k_resolve(const float* __restrict__ gt_cxy,
                          const float* __restrict__ gt_wh,
                          const void*  __restrict__ gt_labels_raw,
                          const float* __restrict__ strides) {
    int t = blockIdx.x * blockDim.x + threadIdx.x;
    if (t >= BS*NG) return;
    int cell = t % NG;
    int b    = t / NG;

    int l, loff, s;
    if (cell < LOFF1)      { l = 0; loff = 0;     s = S0; }
    else if (cell < LOFF2) { l = 1; loff = LOFF1; s = S1; }
    else                   { l = 2; loff = LOFF2; s = S2; }
    int lc = cell - loff;
    int iy = lc / s, ix = lc % s;
    float stride = strides[l];

    int cnt = g_cnt[t];
    int tgt = 0, fg = 0;
    if (cnt == 1) {
        tgt = g_minm[t]; fg = 1;
    } else if (cnt > 1) {
        // faithful to reference: winner is FIRST argmax over ALL gts of metric
        // (includes masked-out gts, exactly as the reference's metric.argmax(1))
        float gx = (float)ix + 0.5f, gy = (float)iy + 0.5f;
        float best = -1e30f; int bm = 0;
        for (int mm = 0; mm < M; mm++) {
            float cx = __fdiv_rn(gt_cxy[(b*M + mm)*2 + 0], stride);
            float cy = __fdiv_rn(gt_cxy[(b*M + mm)*2 + 1], stride);
            float v = fabsf(gx - cx) + fabsf(gy - cy);
            if (v > best) { best = v; bm = mm; }
        }
        int cb = ((b*3 + l)*M + bm)*3;
        if (g_claims[cb] == lc || g_claims[cb+1] == lc || g_claims[cb+2] == lc) {
            tgt = bm; fg = 1;
        } else {
            tgt = 0; fg = 0;  // winner didn't claim -> column all-zero -> argmax 0
        }
    }

    float cx = __fdiv_rn(gt_cxy[(b*M + tgt)*2 + 0], stride);
    float cy = __fdiv_rn(gt_cxy[(b*M + tgt)*2 + 1], stride);
    g_tx[t]  = cx - (float)ix;
    g_ty[t]  = cy - (float)iy;
    g_tw[t]  = __fdiv_rn(gt_wh[(b*M + tgt)*2 + 0], stride);
    g_th[t]  = __fdiv_rn(gt_wh[(b*M + tgt)*2 + 1], stride);
    int li = b*M + tgt;
    g_lab[t] = g_lab64 ? (int)((const long long*)gt_labels_raw)[li]
                       : ((const int*)gt_labels_raw)[li];
    g_fg[t]  = fg;
}

// ---------------- K3 (fused): scores one-hot + txys/whs/anchs/masks --------
// Thread = quarter of an 80-class score row (5 float4 = 80B, coalesced).
// The q==0 thread of each row additionally emits the small per-row records,
// overlapping the 45 MB small stream with the 516 MB score stream.
__global__ void k_out(const float* __restrict__ anc_whs,
                      const float* __restrict__ strides,
                      float* __restrict__ out) {
    int g = blockIdx.x * blockDim.x + threadIdx.x;   // < BS*NA*NG*4 = 6,451,200
    if (g >= BS*NA*NG*4) return;
    int q    = g & 3;          // quarter within the row
    int rr   = g >> 2;         // (b*NA + a)*NG + cell
    int cell = rr % NG;
    int a    = (rr / NG) % NA;
    int b    = rr / (NG*NA);
    int r    = b*NG + cell;
    int lab  = g_lab[r];

    // --- score one-hot quarter ---
    int base = q * 20;
    float4* dst = (float4*)(out + OFF_SC) + (long long)rr * 20 + q * 5;
    #pragma unroll
    for (int j = 0; j < 5; j++) {
        int c0 = base + j*4;
        float4 v;
        v.x = (c0 + 0 == lab) ? 1.0f : 0.0f;
        v.y = (c0 + 1 == lab) ? 1.0f : 0.0f;
        v.z = (c0 + 2 == lab) ? 1.0f : 0.0f;
        v.w = (c0 + 3 == lab) ? 1.0f : 0.0f;
        stcs_f4(dst + j, v);
    }

    // --- small per-row records (one thread per row) ---
    if (q == 0) {
        int l = (cell < LOFF1) ? 0 : (cell < LOFF2) ? 1 : 2;
        float stride = strides[l];
        float ax = __fdiv_rn(anc_whs[(l*3 + a)*2 + 0], stride);
        float ay = __fdiv_rn(anc_whs[(l*3 + a)*2 + 1], stride);

        float tx = g_tx[r], ty = g_ty[r], tw = g_tw[r], th = g_th[r];
        int   fg = g_fg[r];

        float rw = __fdiv_rn(tw, ax), rh = __fdiv_rn(th, ay);
        float mx = fmaxf(fmaxf(rw, __fdiv_rn(1.0f, rw)),
                         fmaxf(rh, __fdiv_rn(1.0f, rh)));
        float maskv = (fg != 0 && mx < 4.0f) ? 1.0f : 0.0f;

        stcs_f2(out + OFF_TXY  + 2LL*rr, make_float2(tx, ty));
        stcs_f2(out + OFF_WH   + 2LL*rr, make_float2(tw, th));
        stcs_f2(out + OFF_ANCH + 2LL*rr, make_float2(ax, ay));
        stcs_f (out + OFF_MASK + rr, maskv);
    }
}

// ---------------- launch ----------------
extern "C" void kernel_launch(void* const* d_in, const int* in_sizes, int n_in,
                              void* d_out, int out_size) {
    const float* anc_whs   = (const float*)d_in[0];
    // d_in[1..3] = grid0/1/2 (recomputed analytically; unused)
    const void*  gt_labels = d_in[4];
    const float* gt_cxy    = (const float*)d_in[5];
    const float* gt_wh     = (const float*)d_in[6];
    const float* strides   = (const float*)d_in[7];
    const float* mask_gt   = (const float*)d_in[8];
    float* out = (float*)d_out;

    const int TPB = 256;
    k_detect <<<1, 128>>>((const int*)gt_labels);
    k_init   <<<(BS*NG + TPB-1)/TPB, TPB>>>();
    k_claim  <<<(BS*3*M + TPB-1)/TPB, TPB>>>(gt_cxy, mask_gt, strides);
    k_resolve<<<(BS*NG + TPB-1)/TPB, TPB>>>(gt_cxy, gt_wh, gt_labels, strides);
    k_out    <<<(BS*NA*NG*4 + TPB-1)/TPB, TPB>>>(anc_whs, strides, out);
}

// round 8
// speedup vs baseline: 1.1349x; 1.1349x over previous
#include <cuda_runtime.h>
#include <cuda_bf16.h>
#include <math.h>

#define BS   16
#define M    256
#define NC   80
#define NA   3
#define S0   160
#define S1   80
#define S2   40
#define NG0  (S0*S0)   // 25600
#define NG1  (S1*S1)   // 6400
#define NG2  (S2*S2)   // 1600
#define NG   (NG0+NG1+NG2)  // 33600
#define LOFF1 NG0
#define LOFF2 (NG0+NG1)

// Flat float32 output layout: [txys | whs | scores | anchs | masks]
#define OFF_TXY  0LL
#define OFF_WH   (3225600LL)
#define OFF_SC   (6451200LL)
#define OFF_ANCH (135475200LL)
#define OFF_MASK (138700800LL)

// ---------------- scratch (device globals; no allocation) ----------------
static __device__ int    g_cnt[BS*NG];
static __device__ int    g_minm[BS*NG];
static __device__ int    g_claims[BS*3*M*3];
static __device__ float4 g_pre[BS*3*M];   // per (b,l,m): {cx/s, cy/s, w/s, h/s}
static __device__ float  g_tx[BS*NG];
static __device__ float  g_ty[BS*NG];
static __device__ float  g_tw[BS*NG];
static __device__ float  g_th[BS*NG];
static __device__ int    g_lab[BS*NG];
static __device__ int    g_fg[BS*NG];
static __device__ int    g_lab64;   // 1 if gt_labels buffer is int64, 0 if int32

// ---------------- K_detect: label dtype sniff (int64 vs int32), parallel ---
// int64 LE with values < NC: every odd 32-bit word is 0. For int32 random
// labels in [0,80), P(128 odd words all zero) = (1/80)^128 ~ 0.
__global__ void k_detect(const int* __restrict__ labels_raw) {
    int i = threadIdx.x;             // 0..127
    int ok = (labels_raw[2*i + 1] == 0) &&
             ((unsigned)labels_raw[2*i] < (unsigned)NC);
    int all = __syncthreads_and(ok);
    if (i == 0) g_lab64 = all;
}

// ---------------- K0: init (must run every replay; graph is replayed) ------
__global__ void k_init() {
    int i = blockIdx.x * blockDim.x + threadIdx.x;
    if (i < BS*NG) { g_cnt[i] = 0; g_minm[i] = 0x7fffffff; }
}

// ---------------- K1: precompute divides + claim 3 nearest cells -----------
__global__ void k_claim(const float* __restrict__ gt_cxy,
                        const float* __restrict__ gt_wh,
                        const float* __restrict__ mask_gt,
                        const float* __restrict__ strides) {
    int t = blockIdx.x * blockDim.x + threadIdx.x;
    if (t >= BS*3*M) return;
    int m = t % M;
    int l = (t / M) % 3;
    int b = t / (M*3);

    float stride = strides[l];
    // precompute ALL divides for this (b,l,m) once (bit-exact __fdiv_rn,
    // identical ops as reference; needed for every m incl. masked-out gts,
    // because the conflict argmax runs over all m)
    float cx = __fdiv_rn(gt_cxy[(b*M + m)*2 + 0], stride);
    float cy = __fdiv_rn(gt_cxy[(b*M + m)*2 + 1], stride);
    float tw = __fdiv_rn(gt_wh [(b*M + m)*2 + 0], stride);
    float th = __fdiv_rn(gt_wh [(b*M + m)*2 + 1], stride);
    g_pre[t] = make_float4(cx, cy, tw, th);

    int cbase = t*3;
    g_claims[cbase+0] = -1; g_claims[cbase+1] = -1; g_claims[cbase+2] = -1;
    if (!(mask_gt[b*M + m] > 0.0f)) return;

    int s    = (l==0) ? S0 : (l==1) ? S1 : S2;
    int loff = (l==0) ? 0  : (l==1) ? LOFF1 : LOFF2;

    int ix0 = (int)floorf(cx); ix0 = min(max(ix0, 0), s-1);
    int iy0 = (int)floorf(cy); iy0 = min(max(iy0, 0), s-1);
    int x0 = max(ix0-2, 0), x1 = min(ix0+2, s-1);
    int y0 = max(iy0-2, 0), y1 = min(iy0+2, s-1);

    // top-3 smallest metric over the 5x5 clamped window.
    // In-window 3rd-best <= 2.0 + eps; any out-of-window metric >= 2.5 - eps,
    // so set equality with full-grid lax.top_k holds. Strict-< insertion with
    // ascending flat-idx scan reproduces top_k's smaller-index tie-break.
    float v0 = 1e30f, v1 = 1e30f, v2 = 1e30f;
    int   i0 = 0,     i1 = 0,     i2 = 0;
    for (int iy = y0; iy <= y1; iy++) {
        float dy = fabsf((float)iy + 0.5f - cy);
        for (int ix = x0; ix <= x1; ix++) {
            // identical fp expression & add order as reference: |dx| + |dy|
            float v = fabsf((float)ix + 0.5f - cx) + dy;
            int idx = iy*s + ix;
            if (v < v0)      { v2=v1; i2=i1; v1=v0; i1=i0; v0=v; i0=idx; }
            else if (v < v1) { v2=v1; i2=i1; v1=v; i1=idx; }
            else if (v < v2) { v2=v; i2=idx; }
        }
    }
    int cells[3] = {i0, i1, i2};
    #pragma unroll
    for (int k = 0; k < 3; k++) {
        int c = cells[k];
        g_claims[cbase + k] = c;
        atomicAdd(&g_cnt [b*NG + loff + c], 1);
        atomicMin(&g_minm[b*NG + loff + c], m);
    }
}

// ---------------- K2: per-cell resolve + gather (divide-free) --------------
__global__ void k_resolve(const void* __restrict__ gt_labels_raw) {
    int t = blockIdx.x * blockDim.x + threadIdx.x;
    if (t >= BS*NG) return;
    int cell = t % NG;
    int b    = t / NG;

    int l, loff, s;
    if (cell < LOFF1)      { l = 0; loff = 0;     s = S0; }
    else if (cell < LOFF2) { l = 1; loff = LOFF1; s = S1; }
    else                   { l = 2; loff = LOFF2; s = S2; }
    int lc = cell - loff;
    int iy = lc / s, ix = lc % s;

    const float4* __restrict__ pre = &g_pre[(b*3 + l)*M];

    int cnt = g_cnt[t];
    int tgt = 0, fg = 0;
    if (cnt == 1) {
        tgt = g_minm[t]; fg = 1;
    } else if (cnt > 1) {
        // faithful to reference: winner is FIRST argmax over ALL gts of metric
        // (includes masked-out gts, exactly as the reference's metric.argmax(1))
        float gx = (float)ix + 0.5f, gy = (float)iy + 0.5f;
        float best = -1e30f; int bm = 0;
        #pragma unroll 4
        for (int mm = 0; mm < M; mm++) {
            float4 p = pre[mm];
            float v = fabsf(gx - p.x) + fabsf(gy - p.y);
            if (v > best) { best = v; bm = mm; }
        }
        int cb = ((b*3 + l)*M + bm)*3;
        if (g_claims[cb] == lc || g_claims[cb+1] == lc || g_claims[cb+2] == lc) {
            tgt = bm; fg = 1;
        } else {
            tgt = 0; fg = 0;  // winner didn't claim -> column all-zero -> argmax 0
        }
    }

    float4 p = pre[tgt];
    g_tx[t]  = p.x - (float)ix;
    g_ty[t]  = p.y - (float)iy;
    g_tw[t]  = p.z;
    g_th[t]  = p.w;
    int li = b*M + tgt;
    g_lab[t] = g_lab64 ? (int)((const long long*)gt_labels_raw)[li]
                       : ((const int*)gt_labels_raw)[li];
    g_fg[t]  = fg;
}

// ---------------- K3 (fused): scores one-hot + txys/whs/anchs/masks --------
// Thread = quarter of an 80-class score row (5 float4 = 80B, coalesced).
// Plain write-back stores this round (A/B vs Round-4's __stcs).
__global__ void k_out(const float* __restrict__ anc_whs,
                      const float* __restrict__ strides,
                      float* __restrict__ out) {
    int g = blockIdx.x * blockDim.x + threadIdx.x;   // < BS*NA*NG*4 = 6,451,200
    if (g >= BS*NA*NG*4) return;
    int q    = g & 3;          // quarter within the row
    int rr   = g >> 2;         // (b*NA + a)*NG + cell
    int cell = rr % NG;
    int a    = (rr / NG) % NA;
    int b    = rr / (NG*NA);
    int r    = b*NG + cell;
    int lab  = g_lab[r];

    // --- score one-hot quarter ---
    int base = q * 20;
    float4* dst = (float4*)(out + OFF_SC) + (long long)rr * 20 + q * 5;
    #pragma unroll
    for (int j = 0; j < 5; j++) {
        int c0 = base + j*4;
        float4 v;
        v.x = (c0 + 0 == lab) ? 1.0f : 0.0f;
        v.y = (c0 + 1 == lab) ? 1.0f : 0.0f;
        v.z = (c0 + 2 == lab) ? 1.0f : 0.0f;
        v.w = (c0 + 3 == lab) ? 1.0f : 0.0f;
        dst[j] = v;
    }

    // --- small per-row records (one thread per row) ---
    if (q == 0) {
        int l = (cell < LOFF1) ? 0 : (cell < LOFF2) ? 1 : 2;
        float stride = strides[l];
        float ax = __fdiv_rn(anc_whs[(l*3 + a)*2 + 0], stride);
        float ay = __fdiv_rn(anc_whs[(l*3 + a)*2 + 1], stride);

        float tx = g_tx[r], ty = g_ty[r], tw = g_tw[r], th = g_th[r];
        int   fg = g_fg[r];

        float rw = __fdiv_rn(tw, ax), rh = __fdiv_rn(th, ay);
        float mx = fmaxf(fmaxf(rw, __fdiv_rn(1.0f, rw)),
                         fmaxf(rh, __fdiv_rn(1.0f, rh)));
        float maskv = (fg != 0 && mx < 4.0f) ? 1.0f : 0.0f;

        ((float2*)(out + OFF_TXY ))[rr] = make_float2(tx, ty);
        ((float2*)(out + OFF_WH  ))[rr] = make_float2(tw, th);
        ((float2*)(out + OFF_ANCH))[rr] = make_float2(ax, ay);
        out[OFF_MASK + rr] = maskv;
    }
}

// ---------------- launch ----------------
extern "C" void kernel_launch(void* const* d_in, const int* in_sizes, int n_in,
                              void* d_out, int out_size) {
    const float* anc_whs   = (const float*)d_in[0];
    // d_in[1..3] = grid0/1/2 (recomputed analytically; unused)
    const void*  gt_labels = d_in[4];
    const float* gt_cxy    = (const float*)d_in[5];
    const float* gt_wh     = (const float*)d_in[6];
    const float* strides   = (const float*)d_in[7];
    const float* mask_gt   = (const float*)d_in[8];
    float* out = (float*)d_out;

    const int TPB = 256;
    k_detect <<<1, 128>>>((const int*)gt_labels);
    k_init   <<<(BS*NG + TPB-1)/TPB, TPB>>>();
    k_claim  <<<(BS*3*M + TPB-1)/TPB, TPB>>>(gt_cxy, gt_wh, mask_gt, strides);
    k_resolve<<<(BS*NG + TPB-1)/TPB, TPB>>>(gt_labels);
    k_out    <<<(BS*NA*NG*4 + TPB-1)/TPB, TPB>>>(anc_whs, strides, out);
}

// round 10
// speedup vs baseline: 1.8154x; 1.5996x over previous
#include <cuda_runtime.h>
#include <cuda_bf16.h>
#include <math.h>

#define BS   16
#define M    256
#define NC   80
#define NA   3
#define S0   160
#define S1   80
#define S2   40
#define NG0  (S0*S0)
#define NG1  (S1*S1)
#define NG2  (S2*S2)
#define NG   (NG0+NG1+NG2)  // 33600
#define LOFF1 NG0
#define LOFF2 (NG0+NG1)

// Flat float32 output layout: [txys | whs | scores | anchs | masks]
#define OFF_TXY  0LL
#define OFF_WH   (3225600LL)
#define OFF_SC   (6451200LL)
#define OFF_ANCH (135475200LL)
#define OFF_MASK (138700800LL)

#define NROWS   (BS*NA*NG)        // 1,612,800
#define SC_F4   (NROWS*20)        // 32,256,000 float4s

// ---------------- scratch (device globals; no allocation) ----------------
static __device__ int    g_cnt[BS*NG];
static __device__ int    g_minm[BS*NG];
static __device__ int    g_claims[BS*3*M*3];
static __device__ float4 g_pre[BS*3*M];   // per (b,l,m): {cx/s, cy/s, w/s, h/s}
static __device__ float  g_tx[BS*NG];
static __device__ float  g_ty[BS*NG];
static __device__ float  g_tw[BS*NG];
static __device__ float  g_th[BS*NG];
static __device__ int    g_lab[BS*NG];
static __device__ int    g_fg[BS*NG];
static __device__ int    g_lab64;          // 1 if labels int64, 0 if int32
static __device__ int    g_nconf;          // contested-cell count
static __device__ int    g_conf[BS*NG];    // contested-cell worklist

// ---------------- K_detect: label dtype sniff (int64 vs int32) -------------
__global__ void k_detect(const int* __restrict__ labels_raw) {
    int i = threadIdx.x;             // 0..127
    int ok = (labels_raw[2*i + 1] == 0) &&
             ((unsigned)labels_raw[2*i] < (unsigned)NC);
    int all = __syncthreads_and(ok);
    if (i == 0) g_lab64 = all;
}

// ---------------- K0: init --------------------------------------------------
__global__ void k_init() {
    int i = blockIdx.x * blockDim.x + threadIdx.x;
    if (i < BS*NG) { g_cnt[i] = 0; g_minm[i] = 0x7fffffff; }
    if (i == 0) g_nconf = 0;
}

// ---------------- K1: precompute divides + claim 3 nearest cells ------------
__global__ void k_claim(const float* __restrict__ gt_cxy,
                        const float* __restrict__ gt_wh,
                        const float* __restrict__ mask_gt,
                        const float* __restrict__ strides) {
    int t = blockIdx.x * blockDim.x + threadIdx.x;
    if (t >= BS*3*M) return;
    int m = t % M;
    int l = (t / M) % 3;
    int b = t / (M*3);

    float stride = strides[l];
    // hoist ALL divides for this (b,l,m) once (bit-exact __fdiv_rn; needed
    // for every m incl. masked-out gts — conflict argmax runs over all m)
    float cx = __fdiv_rn(gt_cxy[(b*M + m)*2 + 0], stride);
    float cy = __fdiv_rn(gt_cxy[(b*M + m)*2 + 1], stride);
    float tw = __fdiv_rn(gt_wh [(b*M + m)*2 + 0], stride);
    float th = __fdiv_rn(gt_wh [(b*M + m)*2 + 1], stride);
    g_pre[t] = make_float4(cx, cy, tw, th);

    int cbase = t*3;
    g_claims[cbase+0] = -1; g_claims[cbase+1] = -1; g_claims[cbase+2] = -1;
    if (!(mask_gt[b*M + m] > 0.0f)) return;

    int s    = (l==0) ? S0 : (l==1) ? S1 : S2;
    int loff = (l==0) ? 0  : (l==1) ? LOFF1 : LOFF2;

    int ix0 = (int)floorf(cx); ix0 = min(max(ix0, 0), s-1);
    int iy0 = (int)floorf(cy); iy0 = min(max(iy0, 0), s-1);
    int x0 = max(ix0-2, 0), x1 = min(ix0+2, s-1);
    int y0 = max(iy0-2, 0), y1 = min(iy0+2, s-1);

    // top-3 smallest metric over the 5x5 clamped window (set-equal to
    // full-grid lax.top_k; strict-< ascending-idx insertion = its tie-break)
    float v0 = 1e30f, v1 = 1e30f, v2 = 1e30f;
    int   i0 = 0,     i1 = 0,     i2 = 0;
    for (int iy = y0; iy <= y1; iy++) {
        float dy = fabsf((float)iy + 0.5f - cy);
        for (int ix = x0; ix <= x1; ix++) {
            float v = fabsf((float)ix + 0.5f - cx) + dy;   // |dx| + |dy|, ref order
            int idx = iy*s + ix;
            if (v < v0)      { v2=v1; i2=i1; v1=v0; i1=i0; v0=v; i0=idx; }
            else if (v < v1) { v2=v1; i2=i1; v1=v; i1=idx; }
            else if (v < v2) { v2=v; i2=idx; }
        }
    }
    int cells[3] = {i0, i1, i2};
    #pragma unroll
    for (int k = 0; k < 3; k++) {
        int c = cells[k];
        g_claims[cbase + k] = c;
        atomicAdd(&g_cnt [b*NG + loff + c], 1);
        atomicMin(&g_minm[b*NG + loff + c], m);
    }
}

// ---------------- K2: fast-path resolve; contested cells -> worklist --------
__global__ void k_resolve(const void* __restrict__ gt_labels_raw) {
    int t = blockIdx.x * blockDim.x + threadIdx.x;
    if (t >= BS*NG) return;
    int cell = t % NG;
    int b    = t / NG;

    int cnt = g_cnt[t];
    if (cnt > 1) {                        // defer to warp-parallel kernel
        int slot = atomicAdd(&g_nconf, 1);
        g_conf[slot] = t;
        return;
    }

    int l, loff, s;
    if (cell < LOFF1)      { l = 0; loff = 0;     s = S0; }
    else if (cell < LOFF2) { l = 1; loff = LOFF1; s = S1; }
    else                   { l = 2; loff = LOFF2; s = S2; }
    int lc = cell - loff;
    int iy = lc / s, ix = lc % s;

    int fg  = (cnt == 1);
    int tgt = fg ? g_minm[t] : 0;

    float4 p = g_pre[(b*3 + l)*M + tgt];
    g_tx[t]  = p.x - (float)ix;
    g_ty[t]  = p.y - (float)iy;
    g_tw[t]  = p.z;
    g_th[t]  = p.w;
    int li = b*M + tgt;
    g_lab[t] = g_lab64 ? (int)((const long long*)gt_labels_raw)[li]
                       : ((const int*)gt_labels_raw)[li];
    g_fg[t]  = fg;
}

// ---------------- K2b: warp-per-contested-cell conflict resolution ----------
__global__ void k_conflict(const void* __restrict__ gt_labels_raw) {
    int gwarp = (blockIdx.x * blockDim.x + threadIdx.x) >> 5;
    int lane  = threadIdx.x & 31;
    int nwarps = (gridDim.x * blockDim.x) >> 5;
    int n = g_nconf;

    for (int w = gwarp; w < n; w += nwarps) {
        int t    = g_conf[w];
        int cell = t % NG;
        int b    = t / NG;
        int l, loff, s;
        if (cell < LOFF1)      { l = 0; loff = 0;     s = S0; }
        else if (cell < LOFF2) { l = 1; loff = LOFF1; s = S1; }
        else                   { l = 2; loff = LOFF2; s = S2; }
        int lc = cell - loff;
        int iy = lc / s, ix = lc % s;

        const float4* __restrict__ pre = &g_pre[(b*3 + l)*M];
        float gx = (float)ix + 0.5f, gy = (float)iy + 0.5f;

        // lane-parallel argmax; ties -> smallest index == jnp first-argmax
        float best = -1e30f; int bm = M;
        #pragma unroll
        for (int mm = lane; mm < M; mm += 32) {
            float4 p = pre[mm];
            float v = fabsf(gx - p.x) + fabsf(gy - p.y);
            if (v > best || (v == best && mm < bm)) { best = v; bm = mm; }
        }
        #pragma unroll
        for (int off = 16; off; off >>= 1) {
            float ov = __shfl_xor_sync(0xffffffffu, best, off);
            int   oi = __shfl_xor_sync(0xffffffffu, bm,   off);
            if (ov > best || (ov == best && oi < bm)) { best = ov; bm = oi; }
        }

        if (lane == 0) {
            int cb = ((b*3 + l)*M + bm)*3;
            int fg = (g_claims[cb] == lc || g_claims[cb+1] == lc ||
                      g_claims[cb+2] == lc);
            int tgt = fg ? bm : 0;   // winner didn't claim -> argmax(all-zero)=0
            float4 p = pre[tgt];
            g_tx[t]  = p.x - (float)ix;
            g_ty[t]  = p.y - (float)iy;
            g_tw[t]  = p.z;
            g_th[t]  = p.w;
            int li = b*M + tgt;
            g_lab[t] = g_lab64 ? (int)((const long long*)gt_labels_raw)[li]
                               : ((const int*)gt_labels_raw)[li];
            g_fg[t]  = fg;
        }
    }
}

// ---------------- K3: txys / whs / anchs / masks (45 MB, lane-contiguous) ---
__global__ void k_small(const float* __restrict__ anc_whs,
                        const float* __restrict__ strides,
                        float* __restrict__ out) {
    int t = blockIdx.x * blockDim.x + threadIdx.x;
    if (t >= NROWS) return;
    int cell = t % NG;
    int a    = (t / NG) % NA;
    int b    = t / (NG*NA);
    int l = (cell < LOFF1) ? 0 : (cell < LOFF2) ? 1 : 2;
    int r = b*NG + cell;

    float stride = strides[l];
    float ax = __fdiv_rn(anc_whs[(l*3 + a)*2 + 0], stride);
    float ay = __fdiv_rn(anc_whs[(l*3 + a)*2 + 1], stride);

    float tx = g_tx[r], ty = g_ty[r], tw = g_tw[r], th = g_th[r];
    int   fg = g_fg[r];

    float rw = __fdiv_rn(tw, ax), rh = __fdiv_rn(th, ay);
    float mx = fmaxf(fmaxf(rw, __fdiv_rn(1.0f, rw)),
                     fmaxf(rh, __fdiv_rn(1.0f, rh)));
    float maskv = (fg != 0 && mx < 4.0f) ? 1.0f : 0.0f;

    ((float2*)(out + OFF_TXY ))[t] = make_float2(tx, ty);
    ((float2*)(out + OFF_WH  ))[t] = make_float2(tw, th);
    ((float2*)(out + OFF_ANCH))[t] = make_float2(ax, ay);
    out[OFF_MASK + t] = maskv;
}

// ---------------- K4: scores one-hot, lane-contiguous stores ----------------
// Each block owns TPB*5 consecutive float4s; store j covers 512 contiguous
// bytes per warp instruction (4 L1 wavefronts = minimum).
__global__ void k_scores(float4* __restrict__ out4) {
    int base = blockIdx.x * (blockDim.x * 5) + threadIdx.x;
    #pragma unroll
    for (int j = 0; j < 5; j++) {
        int idx = base + j * blockDim.x;     // < SC_F4 exactly (no remainder)
        int rr  = idx / 20;                  // score row
        int c0  = (idx - rr*20) * 4;         // starting class of this float4
        int cell = rr % NG;
        int b    = rr / (NG*NA);
        int lab  = g_lab[b*NG + cell];
        float4 v;
        v.x = (c0 + 0 == lab) ? 1.0f : 0.0f;
        v.y = (c0 + 1 == lab) ? 1.0f : 0.0f;
        v.z = (c0 + 2 == lab) ? 1.0f : 0.0f;
        v.w = (c0 + 3 == lab) ? 1.0f : 0.0f;
        out4[idx] = v;
    }
}

// ---------------- launch ----------------
extern "C" void kernel_launch(void* const* d_in, const int* in_sizes, int n_in,
                              void* d_out, int out_size) {
    const float* anc_whs   = (const float*)d_in[0];
    // d_in[1..3] = grid0/1/2 (recomputed analytically; unused)
    const void*  gt_labels = d_in[4];
    const float* gt_cxy    = (const float*)d_in[5];
    const float* gt_wh     = (const float*)d_in[6];
    const float* strides   = (const float*)d_in[7];
    const float* mask_gt   = (const float*)d_in[8];
    float* out = (float*)d_out;

    const int TPB = 256;
    k_detect  <<<1, 128>>>((const int*)gt_labels);
    k_init    <<<(BS*NG + TPB-1)/TPB, TPB>>>();
    k_claim   <<<(BS*3*M + TPB-1)/TPB, TPB>>>(gt_cxy, gt_wh, mask_gt, strides);
    k_resolve <<<(BS*NG + TPB-1)/TPB, TPB>>>(gt_labels);
    k_conflict<<<148, TPB>>>(gt_labels);
    k_small   <<<(NROWS + TPB-1)/TPB, TPB>>>(anc_whs, strides, out);
    k_scores  <<<SC_F4/(TPB*5), TPB>>>((float4*)(out + OFF_SC));
}